// round 8
// baseline (speedup 1.0000x reference)
#include <cuda_runtime.h>
#include <cuda_fp16.h>
#include <math.h>
#include <stdint.h>

// ---------------- problem constants ----------------
#define B_   2048
#define S_   5
#define N_   80
#define E_   592
#define FX_  8
#define FF_  4
#define FE_  8
#define D_   8
#define H_   800
#define NG_  (B_ * S_)            // 10240 graphs
#define XDIM_ (N_ * D_)           // 640
#define EDIM_ (E_ * D_)           // 4736
#define SEQ_  (XDIM_ + EDIM_)     // 5376 (= 84 * 64)
#define G3H_  (3 * H_)            // 2400
#define G3HP_ 2432                // padded to 19*128
#define HPAD_ 832                 // 800 padded to 13*64
#define YPAD_ 4032                // 4000 padded to 63*64
#define MLP1_ 1280
#define OUTN_ 400                 // S_*80
#define OUTNP_ 512                // padded to 4*128

// ---------------- scratch (__device__ globals: allocation-free) ----------------
__device__ __align__(128) __half g_seq16[(size_t)NG_ * SEQ_];
__device__ __align__(128) __half g_wih16[(size_t)G3HP_ * SEQ_];
__device__ __align__(128) __half g_whh16[(size_t)G3HP_ * HPAD_];
__device__ __align__(128) __half g_w1t16[(size_t)MLP1_ * YPAD_];
__device__ __align__(128) __half g_w2t16[(size_t)OUTNP_ * MLP1_];
__device__ __align__(128) __half g_h16[(size_t)B_ * HPAD_];
__device__ __align__(128) __half g_y16[(size_t)B_ * YPAD_];
__device__ __align__(128) __half g_z1 [(size_t)B_ * MLP1_];
__device__ float g_gi [2 * (size_t)NG_ * G3H_];   // split-K=2 partials
__device__ float g_gh [2 * (size_t)B_  * G3H_];   // split-K=2 partials
__device__ float g_o4 [4 * (size_t)B_  * OUTN_];  // mlp2 split-K=4 partials
__device__ float g_h  [(size_t)B_  * H_];

// ---------------- helpers ----------------
__device__ __forceinline__ uint32_t smem_u32(const void* p) {
    uint32_t a;
    asm("{ .reg .u64 t; cvta.to.shared.u64 t, %1; cvt.u32.u64 %0, t; }"
        : "=r"(a) : "l"(p));
    return a;
}
#define SW128(o) ((o) ^ (((o) >> 3) & 0x70))

__device__ __forceinline__ void cp16(uint32_t dst, const void* src) {
    asm volatile("cp.async.cg.shared.global [%0], [%1], 16;" :: "r"(dst), "l"(src));
}
__device__ __forceinline__ void cp_commit() {
    asm volatile("cp.async.commit_group;");
}
__device__ __forceinline__ void ldm4(uint32_t& r0, uint32_t& r1, uint32_t& r2, uint32_t& r3,
                                     uint32_t addr) {
    asm volatile("ldmatrix.sync.aligned.m8n8.x4.shared.b16 {%0,%1,%2,%3}, [%4];"
                 : "=r"(r0), "=r"(r1), "=r"(r2), "=r"(r3) : "r"(addr));
}
__device__ __forceinline__ void mma16816(float* c, const uint32_t* a, const uint32_t* b) {
    asm volatile(
        "mma.sync.aligned.m16n8k16.row.col.f32.f16.f16.f32 "
        "{%0,%1,%2,%3}, {%4,%5,%6,%7}, {%8,%9}, {%0,%1,%2,%3};"
        : "+f"(c[0]), "+f"(c[1]), "+f"(c[2]), "+f"(c[3])
        : "r"(a[0]), "r"(a[1]), "r"(a[2]), "r"(a[3]), "r"(b[0]), "r"(b[1]));
}

// ---------------- GNN: CSR-gather version ----------------
__global__ void __launch_bounds__(256) gnn_kernel(
    const float* __restrict__ x, const int* __restrict__ edge_index,
    const float* __restrict__ edge_f, const float* __restrict__ edge_attr,
    const float* __restrict__ Wx, const float* __restrict__ We,
    const float* __restrict__ Wf, const float* __restrict__ Wedge,
    __half* __restrict__ seq16)
{
    const int g = blockIdx.x;
    const int tid = threadIdx.x;

    const float* xg  = x          + (size_t)g * N_ * FX_;
    const int*   ei  = edge_index + (size_t)g * 2 * E_;
    const float* efg = edge_f     + (size_t)g * E_ * FF_;
    const float* eag = edge_attr  + (size_t)g * E_ * FE_;

    __shared__ float sWx[FX_ * D_];
    __shared__ float sWe[FE_ * D_];
    __shared__ float sWf[FF_ * D_];
    __shared__ float sWedge[(2 * D_ + FE_) * D_];
    __shared__ float s_msg[E_ * D_];
    __shared__ float s_eag[E_ * FE_];
    __shared__ float s_xout[N_ * D_];
    __shared__ short s_src[E_];
    __shared__ short s_dst[E_];
    __shared__ short s_perm[E_];
    __shared__ int   s_cnt[128];
    __shared__ int   s_tmp[128];
    __shared__ int   s_start[128];
    __shared__ int   s_ofs[N_];
    __shared__ int   s_min;

    if (tid < FX_ * D_) sWx[tid] = Wx[tid];
    if (tid < FE_ * D_) sWe[tid] = We[tid];
    if (tid < FF_ * D_) sWf[tid] = Wf[tid];
    if (tid < (2 * D_ + FE_) * D_) sWedge[tid] = Wedge[tid];
    if (tid < 128) s_cnt[tid] = 0;
    if (tid == 0) s_min = 0x7fffffff;
    __syncthreads();

    int lmin = 0x7fffffff;
    for (int e = tid; e < E_; e += 256) lmin = min(lmin, ei[e]);
    atomicMin(&s_min, lmin);
    __syncthreads();
    const int mn = s_min;

    for (int e = tid; e < E_; e += 256) {
        int sI = ei[e]      - mn;
        int dI = ei[E_ + e] - mn;
        if (dI < 0) dI += N_;     // JAX negative-index wrap
        s_src[e] = (short)sI;
        s_dst[e] = (short)dI;
        atomicAdd(&s_cnt[dI], 1);
        float ea[FE_], ef[FF_];
#pragma unroll
        for (int k = 0; k < FE_; k++) { ea[k] = eag[e * FE_ + k]; s_eag[e * FE_ + k] = ea[k]; }
#pragma unroll
        for (int k = 0; k < FF_; k++) ef[k] = efg[e * FF_ + k];
#pragma unroll
        for (int d = 0; d < D_; d++) {
            float m = 0.f;
#pragma unroll
            for (int k = 0; k < FE_; k++) m = fmaf(ea[k], sWe[k * D_ + d], m);
#pragma unroll
            for (int k = 0; k < FF_; k++) m = fmaf(ef[k], sWf[k * D_ + d], m);
            s_msg[e * D_ + d] = fmaxf(m, 0.f);
        }
    }
    __syncthreads();

    if (tid < 128) s_tmp[tid] = s_cnt[tid];
    __syncthreads();
#pragma unroll
    for (int off = 1; off < 128; off <<= 1) {
        int v = 0;
        if (tid < 128) {
            v = s_tmp[tid];
            if (tid >= off) v += s_tmp[tid - off];
        }
        __syncthreads();
        if (tid < 128) s_tmp[tid] = v;
        __syncthreads();
    }
    if (tid < 128) s_start[tid] = (tid == 0) ? 0 : s_tmp[tid - 1];
    if (tid < N_) s_ofs[tid] = (tid == 0) ? 0 : s_tmp[tid - 1];
    __syncthreads();

    for (int e = tid; e < E_; e += 256) {
        int pos = atomicAdd(&s_ofs[(int)s_dst[e]], 1);
        s_perm[pos] = (short)e;
    }
    __syncthreads();

    for (int task = tid; task < N_ * D_; task += 256) {
        const int n = task >> 3;
        const int d = task & 7;
        float agg = 0.f;
        const int s0 = s_start[n];
        const int s1 = s_start[n + 1];
        for (int i = s0; i < s1; i++)
            agg += s_msg[(int)s_perm[i] * D_ + d];
        float t = agg;
#pragma unroll
        for (int k = 0; k < FX_; k++) t = fmaf(xg[n * FX_ + k], sWx[k * D_ + d], t);
        float xo = xg[n * FX_ + d] + fmaxf(t, 0.f);
        s_xout[n * D_ + d] = xo;
        seq16[(size_t)g * SEQ_ + n * D_ + d] = __float2half_rn(xo);
    }
    __syncthreads();

    for (int e = tid; e < E_; e += 256) {
        const int sI = (int)s_src[e], dI = (int)s_dst[e];
        float feat[2 * D_ + FE_];
#pragma unroll
        for (int k = 0; k < D_; k++)  feat[k]          = s_xout[sI * D_ + k];
#pragma unroll
        for (int k = 0; k < D_; k++)  feat[D_ + k]     = s_xout[dI * D_ + k];
#pragma unroll
        for (int k = 0; k < FE_; k++) feat[2 * D_ + k] = s_eag[e * FE_ + k];
#pragma unroll
        for (int d = 0; d < D_; d++) {
            float t = 0.f;
#pragma unroll
            for (int k = 0; k < 2 * D_ + FE_; k++) t = fmaf(feat[k], sWedge[k * D_ + d], t);
            float eo = s_eag[e * FE_ + d] + fmaxf(t, 0.f);
            seq16[(size_t)g * SEQ_ + XDIM_ + e * D_ + d] = __float2half_rn(eo);
        }
    }
}

// ---------------- fused weight conversion ----------------
#define NB_WIH ((G3HP_ * SEQ_ + 255) / 256)
#define NB_WHH ((G3HP_ * HPAD_ + 255) / 256)
#define NB_W1T ((MLP1_ * YPAD_ + 255) / 256)
#define NB_W2T ((OUTNP_ * MLP1_ + 255) / 256)
#define NB_ALL (NB_WIH + NB_WHH + NB_W1T + NB_W2T)

__global__ void __launch_bounds__(256) conv_all(
    const float* __restrict__ w_ih, const float* __restrict__ w_hh,
    const float* __restrict__ mlp_w1, const float* __restrict__ mlp_w2,
    __half* __restrict__ o_wih, __half* __restrict__ o_whh,
    __half* __restrict__ o_w1t, __half* __restrict__ o_w2t)
{
    int b = blockIdx.x;
    if (b < NB_WIH) {
        size_t i = (size_t)b * 256 + threadIdx.x;
        if (i < (size_t)G3HP_ * SEQ_) {
            int n = (int)(i / SEQ_);
            o_wih[i] = __float2half_rn(n < G3H_ ? w_ih[i] : 0.f);
        }
        return;
    }
    b -= NB_WIH;
    if (b < NB_WHH) {
        size_t i = (size_t)b * 256 + threadIdx.x;
        if (i < (size_t)G3HP_ * HPAD_) {
            int n = (int)(i / HPAD_);
            int k = (int)(i % HPAD_);
            o_whh[i] = __float2half_rn((n < G3H_ && k < H_) ? w_hh[(size_t)n * H_ + k] : 0.f);
        }
        return;
    }
    b -= NB_WHH;
    if (b < NB_W1T) {
        size_t i = (size_t)b * 256 + threadIdx.x;
        if (i < (size_t)MLP1_ * YPAD_) {
            int n = (int)(i / YPAD_);
            int k = (int)(i % YPAD_);
            o_w1t[i] = __float2half_rn(k < S_ * H_ ? mlp_w1[(size_t)k * MLP1_ + n] : 0.f);
        }
        return;
    }
    b -= NB_W1T;
    {
        size_t i = (size_t)b * 256 + threadIdx.x;
        if (i < (size_t)OUTNP_ * MLP1_) {
            int n = (int)(i / MLP1_);
            int k = (int)(i % MLP1_);
            o_w2t[i] = __float2half_rn(n < OUTN_ ? mlp_w2[(size_t)k * OUTN_ + n] : 0.f);
        }
    }
}

// ---------------- HMMA TN GEMM, 1-pass fp16, 3-stage pipeline, split-K ----------------
// z = blockIdx.z handles K chunks [z*nchz, min((z+1)*nchz, K/64)).
// Output partial z goes to C + z*M*Nn (or Ch). Bias applied only on z==0.
template <bool OUTH>
__global__ void __launch_bounds__(256, 2) gemm_f16(
    const __half* __restrict__ A, const __half* __restrict__ Bw,
    const float* __restrict__ bias,
    float* __restrict__ C, __half* __restrict__ Ch,
    int M, int Nn, int K, int nchz)
{
    constexpr int TOFF_B = 16384;
    constexpr int TSTAGE = 32768;

    const int z = blockIdx.z;
    const int ch0 = z * nchz;
    const int nch = min(nchz, K / 64 - ch0);
    if (nch <= 0) return;
    A  += ch0 * 64;
    Bw += ch0 * 64;
    const bool dob = (z == 0);

    extern __shared__ char smem[];
    const uint32_t sbase = smem_u32(smem);
    const int tid = threadIdx.x;
    const int wid = tid >> 5, lid = tid & 31;
    const int m0 = blockIdx.y * 128;
    const int n0 = blockIdx.x * 128;

    const int wm = wid & 3;
    const int wn = wid >> 2;

    float acc[2][8][4];
#pragma unroll
    for (int i = 0; i < 2; i++)
#pragma unroll
        for (int j = 0; j < 8; j++)
#pragma unroll
            for (int q = 0; q < 4; q++) acc[i][j][q] = 0.f;

    const int lrow = tid >> 1;
    const int lkc0 = (tid & 1) * 4;

    auto load_stage = [&](int st, int c) {
        const int k0 = c * 64;
        const uint32_t stb = sbase + st * TSTAGE;
#pragma unroll
        for (int i = 0; i < 4; i++) {
            const int kc = lkc0 + i;
            const uint32_t so = SW128((uint32_t)(lrow * 128 + kc * 16));
            cp16(stb + so, A + (size_t)(m0 + lrow) * K + k0 + kc * 8);
            cp16(stb + TOFF_B + so, Bw + (size_t)(n0 + lrow) * K + k0 + kc * 8);
        }
        cp_commit();
    };

    load_stage(0, 0);
    if (nch > 1) load_stage(1, 1);

    const int lt = lid >> 3;
    const int lr = lid & 7;

    int st = 0;
    for (int c = 0; c < nch; c++) {
        if (c + 2 < nch) {
            load_stage((st + 2) % 3, c + 2);
            asm volatile("cp.async.wait_group 2;");
        } else if (c + 1 < nch) {
            asm volatile("cp.async.wait_group 1;");
        } else {
            asm volatile("cp.async.wait_group 0;");
        }
        __syncthreads();

        const uint32_t stb = sbase + st * TSTAGE;
#pragma unroll
        for (int kk = 0; kk < 4; kk++) {
            const int kc = kk * 2 + (lt >> 1);
            uint32_t aH[2][4];
#pragma unroll
            for (int mt = 0; mt < 2; mt++) {
                const int row = wm * 32 + mt * 16 + (lt & 1) * 8 + lr;
                const uint32_t so = SW128((uint32_t)(row * 128 + kc * 16));
                ldm4(aH[mt][0], aH[mt][1], aH[mt][2], aH[mt][3], stb + so);
            }
            uint32_t bf[8][2];
#pragma unroll
            for (int nt = 0; nt < 4; nt++) {
                const int row = wn * 64 + nt * 16 + (lt & 1) * 8 + lr;
                const uint32_t so = SW128((uint32_t)(row * 128 + kc * 16));
                uint32_t q0, q1, q2, q3;
                ldm4(q0, q1, q2, q3, stb + TOFF_B + so);
                bf[nt * 2][0] = q0; bf[nt * 2][1] = q2;
                bf[nt * 2 + 1][0] = q1; bf[nt * 2 + 1][1] = q3;
            }
#pragma unroll
            for (int mt = 0; mt < 2; mt++)
#pragma unroll
                for (int ns = 0; ns < 8; ns++)
                    mma16816(acc[mt][ns], aH[mt], bf[ns]);
        }
        __syncthreads();
        st = (st + 1) % 3;
    }

    // epilogue (z-strided partial output)
    float* Cz = C + (size_t)z * M * Nn;
    __half* Chz = Ch + (size_t)z * M * Nn;
    const int gq = lid >> 2;
    const int tq = lid & 3;
#pragma unroll
    for (int mt = 0; mt < 2; mt++) {
#pragma unroll
        for (int ns = 0; ns < 8; ns++) {
            const int col = n0 + wn * 64 + ns * 8 + tq * 2;
            const int r0 = m0 + wm * 32 + mt * 16 + gq;
            if (col < Nn) {
                const float b0 = dob ? bias[col] : 0.f;
                const float b1 = dob ? bias[col + 1] : 0.f;
                if (OUTH) {
                    __half2 v0 = __floats2half2_rn(acc[mt][ns][0] + b0, acc[mt][ns][1] + b1);
                    __half2 v1 = __floats2half2_rn(acc[mt][ns][2] + b0, acc[mt][ns][3] + b1);
                    *reinterpret_cast<__half2*>(Chz + (size_t)r0 * Nn + col)       = v0;
                    *reinterpret_cast<__half2*>(Chz + (size_t)(r0 + 8) * Nn + col) = v1;
                } else {
                    float2 v0 = make_float2(acc[mt][ns][0] + b0, acc[mt][ns][1] + b1);
                    float2 v1 = make_float2(acc[mt][ns][2] + b0, acc[mt][ns][3] + b1);
                    *reinterpret_cast<float2*>(Cz + (size_t)r0 * Nn + col)       = v0;
                    *reinterpret_cast<float2*>(Cz + (size_t)(r0 + 8) * Nn + col) = v1;
                }
            }
        }
    }
}

// ---------------- GRU pointwise gates (sums split-K partials) ----------------
__global__ void __launch_bounds__(256) gru_gate(
    const float* __restrict__ gi_all, const float* __restrict__ gh,
    const float* __restrict__ gh_bias,
    float* __restrict__ h, __half* __restrict__ h16, __half* __restrict__ y16,
    int t)
{
    const int idx = blockIdx.x * blockDim.x + threadIdx.x;
    if (idx >= B_ * H_) return;
    const int b = idx / H_;
    const int j = idx % H_;

    const float* giA = gi_all + (size_t)(b * S_ + t) * G3H_;
    const float* giB = giA + (size_t)NG_ * G3H_;

    const float ir = giA[j]          + giB[j];
    const float iz = giA[H_ + j]     + giB[H_ + j];
    const float in = giA[2 * H_ + j] + giB[2 * H_ + j];

    float hr, hz, hn, hprev;
    if (t == 0) {
        hr = gh_bias[j]; hz = gh_bias[H_ + j]; hn = gh_bias[2 * H_ + j];
        hprev = 0.f;
    } else {
        const float* ghA = gh + (size_t)b * G3H_;
        const float* ghB = ghA + (size_t)B_ * G3H_;
        hr = ghA[j]          + ghB[j];
        hz = ghA[H_ + j]     + ghB[H_ + j];
        hn = ghA[2 * H_ + j] + ghB[2 * H_ + j];
        hprev = h[idx];
    }

    const float r = 1.f / (1.f + expf(-(ir + hr)));
    const float z = 1.f / (1.f + expf(-(iz + hz)));
    const float n = tanhf(in + r * hn);

    const float hnew = (1.f - z) * n + z * hprev;
    h[idx] = hnew;

    const __half hv = __float2half_rn(hnew);
    h16[(size_t)b * HPAD_ + j] = hv;
    y16[(size_t)b * YPAD_ + t * H_ + j] = hv;
}

// ---------------- sum 4 mlp2 partials -> out ----------------
__global__ void __launch_bounds__(256) add4_kernel(
    const float* __restrict__ p, float* __restrict__ out)
{
    const int i = blockIdx.x * 256 + threadIdx.x;
    if (i >= B_ * OUTN_) return;
    const size_t st = (size_t)B_ * OUTN_;
    out[i] = p[i] + p[st + i] + p[2 * st + i] + p[3 * st + i];
}

// ---------------- launch ----------------
extern "C" void kernel_launch(void* const* d_in, const int* in_sizes, int n_in,
                              void* d_out, int out_size)
{
    const float* x          = (const float*)d_in[0];
    const int*   edge_index = (const int*)  d_in[1];
    const float* edge_f     = (const float*)d_in[2];
    const float* edge_attr  = (const float*)d_in[3];
    const float* Wx         = (const float*)d_in[4];
    const float* We         = (const float*)d_in[5];
    const float* Wf         = (const float*)d_in[6];
    const float* Wedge      = (const float*)d_in[7];
    const float* w_ih       = (const float*)d_in[8];
    const float* w_hh       = (const float*)d_in[9];
    const float* b_ih       = (const float*)d_in[10];
    const float* b_hh       = (const float*)d_in[11];
    const float* mlp_w1     = (const float*)d_in[12];
    const float* mlp_b1     = (const float*)d_in[13];
    const float* mlp_w2     = (const float*)d_in[14];
    const float* mlp_b2     = (const float*)d_in[15];
    float* out = (float*)d_out;

    __half *p_seq, *p_wih, *p_whh, *p_w1t, *p_w2t, *p_h16, *p_y16, *p_z1;
    float *p_gi, *p_gh, *p_o4, *p_h;
    cudaGetSymbolAddress((void**)&p_seq, g_seq16);
    cudaGetSymbolAddress((void**)&p_wih, g_wih16);
    cudaGetSymbolAddress((void**)&p_whh, g_whh16);
    cudaGetSymbolAddress((void**)&p_w1t, g_w1t16);
    cudaGetSymbolAddress((void**)&p_w2t, g_w2t16);
    cudaGetSymbolAddress((void**)&p_h16, g_h16);
    cudaGetSymbolAddress((void**)&p_y16, g_y16);
    cudaGetSymbolAddress((void**)&p_z1,  g_z1);
    cudaGetSymbolAddress((void**)&p_gi,  g_gi);
    cudaGetSymbolAddress((void**)&p_gh,  g_gh);
    cudaGetSymbolAddress((void**)&p_o4,  g_o4);
    cudaGetSymbolAddress((void**)&p_h,   g_h);

    cudaFuncSetAttribute(gemm_f16<false>, cudaFuncAttributeMaxDynamicSharedMemorySize, 3 * 32768);
    cudaFuncSetAttribute(gemm_f16<true>,  cudaFuncAttributeMaxDynamicSharedMemorySize, 3 * 32768);

    // 0) zero pads
    cudaMemsetAsync(p_h16, 0, sizeof(__half) * B_ * HPAD_);
    cudaMemsetAsync(p_y16, 0, sizeof(__half) * B_ * YPAD_);

    // 1) GNN -> seq fp16 ; fused weight conversion
    gnn_kernel<<<NG_, 256>>>(x, edge_index, edge_f, edge_attr, Wx, We, Wf, Wedge, p_seq);
    conv_all<<<NB_ALL, 256>>>(w_ih, w_hh, mlp_w1, mlp_w2, p_wih, p_whh, p_w1t, p_w2t);

    // 2) gi = seq @ w_ih^T + b_ih  [10240, 2400], split-K=2 (84 chunks -> 42+42)
    {
        dim3 grid(G3HP_ / 128, NG_ / 128, 2);   // 19 x 80 x 2
        gemm_f16<false><<<grid, 256, 3 * 32768>>>(p_seq, p_wih, b_ih,
                                                  p_gi, nullptr, NG_, G3H_, SEQ_, 42);
    }

    // 3) GRU recurrence (t=0 skips GEMM; gh split-K=2: 13 chunks -> 7+6)
    {
        dim3 gridh(G3HP_ / 128, B_ / 128, 2);   // 19 x 16 x 2
        for (int t = 0; t < S_; t++) {
            if (t > 0)
                gemm_f16<false><<<gridh, 256, 3 * 32768>>>(p_h16, p_whh, b_hh,
                                                           p_gh, nullptr, B_, G3H_, HPAD_, 7);
            gru_gate<<<(B_ * H_ + 255) / 256, 256>>>(p_gi, p_gh, b_hh,
                                                     p_h, p_h16, p_y16, t);
        }
    }

    // 4) MLP
    {
        dim3 g1(MLP1_ / 128, B_ / 128, 1);      // 10 x 16 (no split)
        gemm_f16<true><<<g1, 256, 3 * 32768>>>(p_y16, p_w1t, mlp_b1,
                                               nullptr, p_z1, B_, MLP1_, YPAD_, 63);
        dim3 g2(OUTNP_ / 128, B_ / 128, 4);     // 4 x 16 x 4 (20 chunks -> 5 each)
        gemm_f16<false><<<g2, 256, 3 * 32768>>>(p_z1, p_w2t, mlp_b2,
                                                p_o4, nullptr, B_, OUTN_, MLP1_, 5);
        add4_kernel<<<(B_ * OUTN_ + 255) / 256, 256>>>(p_o4, out);
    }
}

// round 9
// speedup vs baseline: 1.0183x; 1.0183x over previous
#include <cuda_runtime.h>
#include <cuda_fp16.h>
#include <math.h>
#include <stdint.h>

// ---------------- problem constants ----------------
#define B_   2048
#define S_   5
#define N_   80
#define E_   592
#define FX_  8
#define FF_  4
#define FE_  8
#define D_   8
#define H_   800
#define NG_  (B_ * S_)            // 10240 graphs
#define XDIM_ (N_ * D_)           // 640
#define EDIM_ (E_ * D_)           // 4736
#define SEQ_  (XDIM_ + EDIM_)     // 5376 (= 84 * 64)
#define G3H_  (3 * H_)            // 2400
#define G3HP_ 2432                // padded to 19*128
#define HPAD_ 832                 // 800 padded to 13*64
#define YPAD_ 4032                // 4000 padded to 63*64
#define MLP1_ 1280
#define OUTN_ 400                 // S_*80
#define OUTNP_ 512                // padded to 4*128

// ---------------- scratch (__device__ globals: allocation-free) ----------------
__device__ __align__(128) __half g_seq16[(size_t)NG_ * SEQ_];
__device__ __align__(128) __half g_wih16[(size_t)G3HP_ * SEQ_];
__device__ __align__(128) __half g_whh16[(size_t)G3HP_ * HPAD_];
__device__ __align__(128) __half g_w1t16[(size_t)MLP1_ * YPAD_];
__device__ __align__(128) __half g_w2t16[(size_t)OUTNP_ * MLP1_];
__device__ __align__(128) __half g_h16[(size_t)B_ * HPAD_];
__device__ __align__(128) __half g_y16[(size_t)B_ * YPAD_];
__device__ __align__(128) __half g_z1 [(size_t)B_ * MLP1_];
__device__ float g_gi [(size_t)NG_ * G3H_];
__device__ float g_gh [(size_t)B_  * G3H_];
__device__ float g_o4 [4 * (size_t)B_ * OUTN_];   // mlp2 split-K=4 partials
__device__ float g_h  [(size_t)B_  * H_];

// ---------------- helpers ----------------
__device__ __forceinline__ uint32_t smem_u32(const void* p) {
    uint32_t a;
    asm("{ .reg .u64 t; cvta.to.shared.u64 t, %1; cvt.u32.u64 %0, t; }"
        : "=r"(a) : "l"(p));
    return a;
}
#define SW128(o) ((o) ^ (((o) >> 3) & 0x70))

__device__ __forceinline__ void cp16(uint32_t dst, const void* src) {
    asm volatile("cp.async.cg.shared.global [%0], [%1], 16;" :: "r"(dst), "l"(src));
}
__device__ __forceinline__ void cp_commit() {
    asm volatile("cp.async.commit_group;");
}
__device__ __forceinline__ void ldm4(uint32_t& r0, uint32_t& r1, uint32_t& r2, uint32_t& r3,
                                     uint32_t addr) {
    asm volatile("ldmatrix.sync.aligned.m8n8.x4.shared.b16 {%0,%1,%2,%3}, [%4];"
                 : "=r"(r0), "=r"(r1), "=r"(r2), "=r"(r3) : "r"(addr));
}
__device__ __forceinline__ void mma16816(float* c, const uint32_t* a, const uint32_t* b) {
    asm volatile(
        "mma.sync.aligned.m16n8k16.row.col.f32.f16.f16.f32 "
        "{%0,%1,%2,%3}, {%4,%5,%6,%7}, {%8,%9}, {%0,%1,%2,%3};"
        : "+f"(c[0]), "+f"(c[1]), "+f"(c[2]), "+f"(c[3])
        : "r"(a[0]), "r"(a[1]), "r"(a[2]), "r"(a[3]), "r"(b[0]), "r"(b[1]));
}

// ---------------- GNN: CSR-gather version ----------------
__global__ void __launch_bounds__(256) gnn_kernel(
    const float* __restrict__ x, const int* __restrict__ edge_index,
    const float* __restrict__ edge_f, const float* __restrict__ edge_attr,
    const float* __restrict__ Wx, const float* __restrict__ We,
    const float* __restrict__ Wf, const float* __restrict__ Wedge,
    __half* __restrict__ seq16)
{
    const int g = blockIdx.x;
    const int tid = threadIdx.x;

    const float* xg  = x          + (size_t)g * N_ * FX_;
    const int*   ei  = edge_index + (size_t)g * 2 * E_;
    const float* efg = edge_f     + (size_t)g * E_ * FF_;
    const float* eag = edge_attr  + (size_t)g * E_ * FE_;

    __shared__ float sWx[FX_ * D_];
    __shared__ float sWe[FE_ * D_];
    __shared__ float sWf[FF_ * D_];
    __shared__ float sWedge[(2 * D_ + FE_) * D_];
    __shared__ float s_msg[E_ * D_];
    __shared__ float s_eag[E_ * FE_];
    __shared__ float s_xout[N_ * D_];
    __shared__ short s_src[E_];
    __shared__ short s_dst[E_];
    __shared__ short s_perm[E_];
    __shared__ int   s_cnt[128];
    __shared__ int   s_tmp[128];
    __shared__ int   s_start[128];
    __shared__ int   s_ofs[N_];
    __shared__ int   s_min;

    if (tid < FX_ * D_) sWx[tid] = Wx[tid];
    if (tid < FE_ * D_) sWe[tid] = We[tid];
    if (tid < FF_ * D_) sWf[tid] = Wf[tid];
    if (tid < (2 * D_ + FE_) * D_) sWedge[tid] = Wedge[tid];
    if (tid < 128) s_cnt[tid] = 0;
    if (tid == 0) s_min = 0x7fffffff;
    __syncthreads();

    int lmin = 0x7fffffff;
    for (int e = tid; e < E_; e += 256) lmin = min(lmin, ei[e]);
    atomicMin(&s_min, lmin);
    __syncthreads();
    const int mn = s_min;

    for (int e = tid; e < E_; e += 256) {
        int sI = ei[e]      - mn;
        int dI = ei[E_ + e] - mn;
        if (dI < 0) dI += N_;     // JAX negative-index wrap
        s_src[e] = (short)sI;
        s_dst[e] = (short)dI;
        atomicAdd(&s_cnt[dI], 1);
        float ea[FE_], ef[FF_];
#pragma unroll
        for (int k = 0; k < FE_; k++) { ea[k] = eag[e * FE_ + k]; s_eag[e * FE_ + k] = ea[k]; }
#pragma unroll
        for (int k = 0; k < FF_; k++) ef[k] = efg[e * FF_ + k];
#pragma unroll
        for (int d = 0; d < D_; d++) {
            float m = 0.f;
#pragma unroll
            for (int k = 0; k < FE_; k++) m = fmaf(ea[k], sWe[k * D_ + d], m);
#pragma unroll
            for (int k = 0; k < FF_; k++) m = fmaf(ef[k], sWf[k * D_ + d], m);
            s_msg[e * D_ + d] = fmaxf(m, 0.f);
        }
    }
    __syncthreads();

    if (tid < 128) s_tmp[tid] = s_cnt[tid];
    __syncthreads();
#pragma unroll
    for (int off = 1; off < 128; off <<= 1) {
        int v = 0;
        if (tid < 128) {
            v = s_tmp[tid];
            if (tid >= off) v += s_tmp[tid - off];
        }
        __syncthreads();
        if (tid < 128) s_tmp[tid] = v;
        __syncthreads();
    }
    if (tid < 128) s_start[tid] = (tid == 0) ? 0 : s_tmp[tid - 1];
    if (tid < N_) s_ofs[tid] = (tid == 0) ? 0 : s_tmp[tid - 1];
    __syncthreads();

    for (int e = tid; e < E_; e += 256) {
        int pos = atomicAdd(&s_ofs[(int)s_dst[e]], 1);
        s_perm[pos] = (short)e;
    }
    __syncthreads();

    for (int task = tid; task < N_ * D_; task += 256) {
        const int n = task >> 3;
        const int d = task & 7;
        float agg = 0.f;
        const int s0 = s_start[n];
        const int s1 = s_start[n + 1];
        for (int i = s0; i < s1; i++)
            agg += s_msg[(int)s_perm[i] * D_ + d];
        float t = agg;
#pragma unroll
        for (int k = 0; k < FX_; k++) t = fmaf(xg[n * FX_ + k], sWx[k * D_ + d], t);
        float xo = xg[n * FX_ + d] + fmaxf(t, 0.f);
        s_xout[n * D_ + d] = xo;
        seq16[(size_t)g * SEQ_ + n * D_ + d] = __float2half_rn(xo);
    }
    __syncthreads();

    for (int e = tid; e < E_; e += 256) {
        const int sI = (int)s_src[e], dI = (int)s_dst[e];
        float feat[2 * D_ + FE_];
#pragma unroll
        for (int k = 0; k < D_; k++)  feat[k]          = s_xout[sI * D_ + k];
#pragma unroll
        for (int k = 0; k < D_; k++)  feat[D_ + k]     = s_xout[dI * D_ + k];
#pragma unroll
        for (int k = 0; k < FE_; k++) feat[2 * D_ + k] = s_eag[e * FE_ + k];
#pragma unroll
        for (int d = 0; d < D_; d++) {
            float t = 0.f;
#pragma unroll
            for (int k = 0; k < 2 * D_ + FE_; k++) t = fmaf(feat[k], sWedge[k * D_ + d], t);
            float eo = s_eag[e * FE_ + d] + fmaxf(t, 0.f);
            seq16[(size_t)g * SEQ_ + XDIM_ + e * D_ + d] = __float2half_rn(eo);
        }
    }
}

// ---------------- direct weight conversion (wih + whh, coalesced) ----------------
#define NB_WIH ((G3HP_ * SEQ_ + 255) / 256)
#define NB_WHH ((G3HP_ * HPAD_ + 255) / 256)
#define NB_CV  (NB_WIH + NB_WHH)

__global__ void __launch_bounds__(256) conv_direct(
    const float* __restrict__ w_ih, const float* __restrict__ w_hh,
    __half* __restrict__ o_wih, __half* __restrict__ o_whh)
{
    int b = blockIdx.x;
    if (b < NB_WIH) {
        size_t i = (size_t)b * 256 + threadIdx.x;
        if (i < (size_t)G3HP_ * SEQ_) {
            int n = (int)(i / SEQ_);
            o_wih[i] = __float2half_rn(n < G3H_ ? w_ih[i] : 0.f);
        }
        return;
    }
    b -= NB_WIH;
    {
        size_t i = (size_t)b * 256 + threadIdx.x;
        if (i < (size_t)G3HP_ * HPAD_) {
            int n = (int)(i / HPAD_);
            int k = (int)(i % HPAD_);
            o_whh[i] = __float2half_rn((n < G3H_ && k < H_) ? w_hh[(size_t)n * H_ + k] : 0.f);
        }
    }
}

// ---------------- tiled transpose-convert: dst[i,j] = fp16(src[j,i]), zero-padded ----------------
// src [R, C] fp32 ; dst [Dr, Dc] fp16 with Dr >= C, Dc >= R. 32x32 tiles, coalesced both sides.
__global__ void __launch_bounds__(256) trans_conv(
    const float* __restrict__ src, __half* __restrict__ dst,
    int R, int C, int Dr, int Dc)
{
    __shared__ float tile[32][33];
    const int j0 = blockIdx.x * 32;   // dst col base == src row base
    const int i0 = blockIdx.y * 32;   // dst row base == src col base
    const int tx = threadIdx.x & 31;
    const int ty = threadIdx.x >> 5;  // 0..7

    for (int r = ty; r < 32; r += 8) {
        float v = 0.f;
        const int j = j0 + r, i = i0 + tx;
        if (j < R && i < C) v = src[(size_t)j * C + i];
        tile[r][tx] = v;
    }
    __syncthreads();
    for (int r = ty; r < 32; r += 8) {
        const int i = i0 + r, j = j0 + tx;
        if (i < Dr && j < Dc)
            dst[(size_t)i * Dc + j] = __float2half_rn(tile[tx][r]);
    }
}

// ---------------- HMMA TN GEMM, 1-pass fp16, 3-stage pipeline, optional split-K ----------------
// z = blockIdx.z handles K chunks [z*nchz, ...). Partial z -> C + z*M*Nn. Bias only on z==0.
template <bool OUTH>
__global__ void __launch_bounds__(256, 2) gemm_f16(
    const __half* __restrict__ A, const __half* __restrict__ Bw,
    const float* __restrict__ bias,
    float* __restrict__ C, __half* __restrict__ Ch,
    int M, int Nn, int K, int nchz)
{
    constexpr int TOFF_B = 16384;
    constexpr int TSTAGE = 32768;

    const int z = blockIdx.z;
    const int ch0 = z * nchz;
    const int nch = min(nchz, K / 64 - ch0);
    if (nch <= 0) return;
    A  += ch0 * 64;
    Bw += ch0 * 64;
    const bool dob = (z == 0);

    extern __shared__ char smem[];
    const uint32_t sbase = smem_u32(smem);
    const int tid = threadIdx.x;
    const int wid = tid >> 5, lid = tid & 31;
    const int m0 = blockIdx.y * 128;
    const int n0 = blockIdx.x * 128;

    const int wm = wid & 3;
    const int wn = wid >> 2;

    float acc[2][8][4];
#pragma unroll
    for (int i = 0; i < 2; i++)
#pragma unroll
        for (int j = 0; j < 8; j++)
#pragma unroll
            for (int q = 0; q < 4; q++) acc[i][j][q] = 0.f;

    const int lrow = tid >> 1;
    const int lkc0 = (tid & 1) * 4;

    auto load_stage = [&](int st, int c) {
        const int k0 = c * 64;
        const uint32_t stb = sbase + st * TSTAGE;
#pragma unroll
        for (int i = 0; i < 4; i++) {
            const int kc = lkc0 + i;
            const uint32_t so = SW128((uint32_t)(lrow * 128 + kc * 16));
            cp16(stb + so, A + (size_t)(m0 + lrow) * K + k0 + kc * 8);
            cp16(stb + TOFF_B + so, Bw + (size_t)(n0 + lrow) * K + k0 + kc * 8);
        }
        cp_commit();
    };

    load_stage(0, 0);
    if (nch > 1) load_stage(1, 1);

    const int lt = lid >> 3;
    const int lr = lid & 7;

    int st = 0;
    for (int c = 0; c < nch; c++) {
        if (c + 2 < nch) {
            load_stage((st + 2) % 3, c + 2);
            asm volatile("cp.async.wait_group 2;");
        } else if (c + 1 < nch) {
            asm volatile("cp.async.wait_group 1;");
        } else {
            asm volatile("cp.async.wait_group 0;");
        }
        __syncthreads();

        const uint32_t stb = sbase + st * TSTAGE;
#pragma unroll
        for (int kk = 0; kk < 4; kk++) {
            const int kc = kk * 2 + (lt >> 1);
            uint32_t aH[2][4];
#pragma unroll
            for (int mt = 0; mt < 2; mt++) {
                const int row = wm * 32 + mt * 16 + (lt & 1) * 8 + lr;
                const uint32_t so = SW128((uint32_t)(row * 128 + kc * 16));
                ldm4(aH[mt][0], aH[mt][1], aH[mt][2], aH[mt][3], stb + so);
            }
            uint32_t bf[8][2];
#pragma unroll
            for (int nt = 0; nt < 4; nt++) {
                const int row = wn * 64 + nt * 16 + (lt & 1) * 8 + lr;
                const uint32_t so = SW128((uint32_t)(row * 128 + kc * 16));
                uint32_t q0, q1, q2, q3;
                ldm4(q0, q1, q2, q3, stb + TOFF_B + so);
                bf[nt * 2][0] = q0; bf[nt * 2][1] = q2;
                bf[nt * 2 + 1][0] = q1; bf[nt * 2 + 1][1] = q3;
            }
#pragma unroll
            for (int mt = 0; mt < 2; mt++)
#pragma unroll
                for (int ns = 0; ns < 8; ns++)
                    mma16816(acc[mt][ns], aH[mt], bf[ns]);
        }
        __syncthreads();
        st = (st + 1) % 3;
    }

    float* Cz = C + (size_t)z * M * Nn;
    __half* Chz = Ch + (size_t)z * M * Nn;
    const int gq = lid >> 2;
    const int tq = lid & 3;
#pragma unroll
    for (int mt = 0; mt < 2; mt++) {
#pragma unroll
        for (int ns = 0; ns < 8; ns++) {
            const int col = n0 + wn * 64 + ns * 8 + tq * 2;
            const int r0 = m0 + wm * 32 + mt * 16 + gq;
            if (col < Nn) {
                const float b0 = dob ? bias[col] : 0.f;
                const float b1 = dob ? bias[col + 1] : 0.f;
                if (OUTH) {
                    __half2 v0 = __floats2half2_rn(acc[mt][ns][0] + b0, acc[mt][ns][1] + b1);
                    __half2 v1 = __floats2half2_rn(acc[mt][ns][2] + b0, acc[mt][ns][3] + b1);
                    *reinterpret_cast<__half2*>(Chz + (size_t)r0 * Nn + col)       = v0;
                    *reinterpret_cast<__half2*>(Chz + (size_t)(r0 + 8) * Nn + col) = v1;
                } else {
                    float2 v0 = make_float2(acc[mt][ns][0] + b0, acc[mt][ns][1] + b1);
                    float2 v1 = make_float2(acc[mt][ns][2] + b0, acc[mt][ns][3] + b1);
                    *reinterpret_cast<float2*>(Cz + (size_t)r0 * Nn + col)       = v0;
                    *reinterpret_cast<float2*>(Cz + (size_t)(r0 + 8) * Nn + col) = v1;
                }
            }
        }
    }
}

// ---------------- GRU pointwise gates ----------------
__global__ void __launch_bounds__(256) gru_gate(
    const float* __restrict__ gi_all, const float* __restrict__ gh,
    const float* __restrict__ gh_bias,
    float* __restrict__ h, __half* __restrict__ h16, __half* __restrict__ y16,
    int t)
{
    const int idx = blockIdx.x * blockDim.x + threadIdx.x;
    if (idx >= B_ * H_) return;
    const int b = idx / H_;
    const int j = idx % H_;

    const float* gi = gi_all + (size_t)(b * S_ + t) * G3H_;

    float hr, hz, hn, hprev;
    if (t == 0) {
        hr = gh_bias[j]; hz = gh_bias[H_ + j]; hn = gh_bias[2 * H_ + j];
        hprev = 0.f;
    } else {
        const float* ghb = gh + (size_t)b * G3H_;
        hr = ghb[j]; hz = ghb[H_ + j]; hn = ghb[2 * H_ + j];
        hprev = h[idx];
    }

    const float ir = gi[j], iz = gi[H_ + j], in = gi[2 * H_ + j];

    const float r = 1.f / (1.f + expf(-(ir + hr)));
    const float z = 1.f / (1.f + expf(-(iz + hz)));
    const float n = tanhf(in + r * hn);

    const float hnew = (1.f - z) * n + z * hprev;
    h[idx] = hnew;

    const __half hv = __float2half_rn(hnew);
    h16[(size_t)b * HPAD_ + j] = hv;
    y16[(size_t)b * YPAD_ + t * H_ + j] = hv;
}

// ---------------- sum 4 mlp2 partials -> out ----------------
__global__ void __launch_bounds__(256) add4_kernel(
    const float* __restrict__ p, float* __restrict__ out)
{
    const int i = blockIdx.x * 256 + threadIdx.x;
    if (i >= B_ * OUTN_) return;
    const size_t st = (size_t)B_ * OUTN_;
    out[i] = p[i] + p[st + i] + p[2 * st + i] + p[3 * st + i];
}

// ---------------- launch ----------------
extern "C" void kernel_launch(void* const* d_in, const int* in_sizes, int n_in,
                              void* d_out, int out_size)
{
    const float* x          = (const float*)d_in[0];
    const int*   edge_index = (const int*)  d_in[1];
    const float* edge_f     = (const float*)d_in[2];
    const float* edge_attr  = (const float*)d_in[3];
    const float* Wx         = (const float*)d_in[4];
    const float* We         = (const float*)d_in[5];
    const float* Wf         = (const float*)d_in[6];
    const float* Wedge      = (const float*)d_in[7];
    const float* w_ih       = (const float*)d_in[8];
    const float* w_hh       = (const float*)d_in[9];
    const float* b_ih       = (const float*)d_in[10];
    const float* b_hh       = (const float*)d_in[11];
    const float* mlp_w1     = (const float*)d_in[12];
    const float* mlp_b1     = (const float*)d_in[13];
    const float* mlp_w2     = (const float*)d_in[14];
    const float* mlp_b2     = (const float*)d_in[15];
    float* out = (float*)d_out;

    __half *p_seq, *p_wih, *p_whh, *p_w1t, *p_w2t, *p_h16, *p_y16, *p_z1;
    float *p_gi, *p_gh, *p_o4, *p_h;
    cudaGetSymbolAddress((void**)&p_seq, g_seq16);
    cudaGetSymbolAddress((void**)&p_wih, g_wih16);
    cudaGetSymbolAddress((void**)&p_whh, g_whh16);
    cudaGetSymbolAddress((void**)&p_w1t, g_w1t16);
    cudaGetSymbolAddress((void**)&p_w2t, g_w2t16);
    cudaGetSymbolAddress((void**)&p_h16, g_h16);
    cudaGetSymbolAddress((void**)&p_y16, g_y16);
    cudaGetSymbolAddress((void**)&p_z1,  g_z1);
    cudaGetSymbolAddress((void**)&p_gi,  g_gi);
    cudaGetSymbolAddress((void**)&p_gh,  g_gh);
    cudaGetSymbolAddress((void**)&p_o4,  g_o4);
    cudaGetSymbolAddress((void**)&p_h,   g_h);

    cudaFuncSetAttribute(gemm_f16<false>, cudaFuncAttributeMaxDynamicSharedMemorySize, 3 * 32768);
    cudaFuncSetAttribute(gemm_f16<true>,  cudaFuncAttributeMaxDynamicSharedMemorySize, 3 * 32768);

    // 0) zero pads
    cudaMemsetAsync(p_h16, 0, sizeof(__half) * B_ * HPAD_);
    cudaMemsetAsync(p_y16, 0, sizeof(__half) * B_ * YPAD_);

    // 1) GNN -> seq fp16 ; weight conversions (direct + coalesced tiled transposes)
    gnn_kernel<<<NG_, 256>>>(x, edge_index, edge_f, edge_attr, Wx, We, Wf, Wedge, p_seq);
    conv_direct<<<NB_CV, 256>>>(w_ih, w_hh, p_wih, p_whh);
    {
        dim3 gt1((YPAD_ + 31) / 32, MLP1_ / 32);   // w1 [4000,1280] -> [1280,4032]
        trans_conv<<<gt1, 256>>>(mlp_w1, p_w1t, S_ * H_, MLP1_, MLP1_, YPAD_);
        dim3 gt2((MLP1_ + 31) / 32, OUTNP_ / 32);  // w2 [1280,400] -> [512,1280]
        trans_conv<<<gt2, 256>>>(mlp_w2, p_w2t, MLP1_, OUTN_, OUTNP_, MLP1_);
    }

    // 2) gi = seq @ w_ih^T + b_ih  [10240, 2400] (no split-K)
    {
        dim3 grid(G3HP_ / 128, NG_ / 128, 1);   // 19 x 80
        gemm_f16<false><<<grid, 256, 3 * 32768>>>(p_seq, p_wih, b_ih,
                                                  p_gi, nullptr, NG_, G3H_, SEQ_, 84);
    }

    // 3) GRU recurrence (t=0 skips GEMM: gh == b_hh since h=0)
    {
        dim3 gridh(G3HP_ / 128, B_ / 128, 1);   // 19 x 16
        for (int t = 0; t < S_; t++) {
            if (t > 0)
                gemm_f16<false><<<gridh, 256, 3 * 32768>>>(p_h16, p_whh, b_hh,
                                                           p_gh, nullptr, B_, G3H_, HPAD_, 13);
            gru_gate<<<(B_ * H_ + 255) / 256, 256>>>(p_gi, p_gh, b_hh,
                                                     p_h, p_h16, p_y16, t);
        }
    }

    // 4) MLP (mlp1 no split; mlp2 split-K=4 to fill the chip)
    {
        dim3 g1(MLP1_ / 128, B_ / 128, 1);      // 10 x 16
        gemm_f16<true><<<g1, 256, 3 * 32768>>>(p_y16, p_w1t, mlp_b1,
                                               nullptr, p_z1, B_, MLP1_, YPAD_, 63);
        dim3 g2(OUTNP_ / 128, B_ / 128, 4);     // 4 x 16 x 4 (20 chunks -> 5 each)
        gemm_f16<false><<<g2, 256, 3 * 32768>>>(p_z1, p_w2t, mlp_b2,
                                                p_o4, nullptr, B_, OUTN_, MLP1_, 5);
        add4_kernel<<<(B_ * OUTN_ + 255) / 256, 256>>>(p_o4, out);
    }
}